// round 4
// baseline (speedup 1.0000x reference)
#include <cuda_runtime.h>

// Fixed shapes: B=32,S=256 -> NTOK=8192; D=16; V=8192; n_steps=8
#define NTOK 8192
#define DD   16
#define VV   8192
#define VC   256            // V-chunk staged in SMEM
#define TPT  4              // tokens per thread
#define LANES 32
#define SLICE 8             // V-range split (warps)
#define NTHREADS 256        // LANES * SLICE
#define TPC (LANES*TPT)     // 128 tokens per CTA
#define NTB (NTOK/TPC)      // 64 token blocks
#define VSPLIT 8
#define VPER (VV/VSPLIT)    // 1024
#define NBLOCKS (NTB*VSPLIT)// 512 CTAs

#define INVT  1.25f
#define LOG2E 1.4426950408889634f
#define LSCALE (INVT*LOG2E)

typedef unsigned long long u64;

// Scratch (allocation-free rule)
__device__ float g_x   [NTOK*DD];
__device__ float g_xm  [NTOK*DD];
__device__ float g_pack[VV*32];          // [v][0..15]=LSCALE*W[:,v], [v][16..31]=CB[v,:]
__device__ float g_part[VSPLIT*17*NTOK]; // per-V-slot partials: [(slot*17+i)*NTOK + tok]
__device__ int   g_ticket[NTB];          // zero-init; reset by finalizer each launch

__device__ __forceinline__ float ex2f(float x) {
    float r; asm("ex2.approx.ftz.f32 %0, %1;" : "=f"(r) : "f"(x)); return r;
}
#define FMA2(d,a,b,c) asm("fma.rn.f32x2 %0, %1, %2, %3;" : "=l"(d) : "l"(a), "l"(b), "l"(c))
#define MUL2(d,a,b)   asm("mul.rn.f32x2 %0, %1, %2;"     : "=l"(d) : "l"(a), "l"(b))
#define ADD2(d,a,b)   asm("add.rn.f32x2 %0, %1, %2;"     : "=l"(d) : "l"(a), "l"(b))
#define UNPK2(lo,hi,v) asm("mov.b64 {%0,%1}, %2;" : "=f"(lo), "=f"(hi) : "l"(v))
#define PCK2(v,lo,hi)  asm("mov.b64 %0, {%1,%2};" : "=l"(v) : "f"(lo), "f"(hi))

__global__ void copy_kernel(const float* __restrict__ src, int n) {
    int i = blockIdx.x * blockDim.x + threadIdx.x;
    if (i < n) g_x[i] = src[i];
}

__global__ void prep_kernel(const float* __restrict__ W,   // [DD][VV]
                            const float* __restrict__ CB)  // [VV][DD]
{
    int v = blockIdx.x * blockDim.x + threadIdx.x;
    if (v >= VV) return;
    float wcol[DD];
    #pragma unroll
    for (int d = 0; d < DD; d++) wcol[d] = W[d*VV + v] * LSCALE;
    float4* dst = (float4*)(g_pack + v*32);
    const float4* cb = (const float4*)(CB + v*DD);
    #pragma unroll
    for (int i = 0; i < 4; i++) {
        float4 w4; w4.x=wcol[4*i]; w4.y=wcol[4*i+1]; w4.z=wcol[4*i+2]; w4.w=wcol[4*i+3];
        dst[i]   = w4;
        dst[4+i] = cb[i];
    }
}

// velocity = (softmax((x@W + b + t*tp)/T) @ CB - x)/(1-t+eps); x_out = g_x + coef*v
// No max-subtraction (|log2 logits| <~ 40, fp32-safe).
// Each CTA handles 128 tokens x 1/8 of V; last CTA per tokblock combines.
__global__ __launch_bounds__(NTHREADS)
void velocity_kernel(const float* __restrict__ b,
                     const float* __restrict__ tp,
                     float t, float coef, int mode)
{
    __shared__ __align__(16) float smem[VC*32 + VC];
    __shared__ int flag;
    float* csm = smem + VC*32;

    const float* x_in  = mode ? g_xm : g_x;
    float*       x_out = mode ? g_x  : g_xm;

    int tid   = threadIdx.x;
    int lane  = tid & 31;
    int slice = tid >> 5;                 // warp index 0..7
    int tb    = blockIdx.x >> 3;          // token block 0..63
    int slot  = blockIdx.x & 7;           // V slot 0..7
    int tok0  = tb*TPC + lane;            // tokens tok0 + 32*j

    // 4 tokens' x as packed f32x2 pairs (8 u64 each)
    u64 xr[TPT][8], mur[TPT][8];
    u64 zero2; PCK2(zero2, 0.f, 0.f);
    float s[TPT];
    #pragma unroll
    for (int j = 0; j < TPT; j++) {
        const ulonglong2* A = (const ulonglong2*)(x_in + (tok0 + 32*j)*DD);
        #pragma unroll
        for (int i = 0; i < 4; i++) {
            ulonglong2 v2 = A[i];
            xr[j][2*i] = v2.x; xr[j][2*i+1] = v2.y;
        }
        #pragma unroll
        for (int i = 0; i < 8; i++) mur[j][i] = zero2;
        s[j] = 0.f;
    }

    int cbeg = slot * VPER;
    for (int c0 = cbeg; c0 < cbeg + VPER; c0 += VC) {
        __syncthreads();
        {   // stage packed chunk: 2048 float4 over 256 threads
            const float4* src = (const float4*)(g_pack + (size_t)c0*32);
            float4* dst = (float4*)smem;
            #pragma unroll
            for (int j = 0; j < 8; j++)
                dst[tid + j*NTHREADS] = src[tid + j*NTHREADS];
        }
        csm[tid] = (b[c0+tid] + t*tp[c0+tid]) * LSCALE;   // NTHREADS == VC
        __syncthreads();

        int vbeg = slice * (VC/SLICE);
        #pragma unroll 4
        for (int vi = 0; vi < VC/SLICE; vi++) {
            int v = vbeg + vi;
            const ulonglong2* p = (const ulonglong2*)(smem + v*32);  // warp-broadcast
            ulonglong2 P0=p[0], P1=p[1], P2=p[2], P3=p[3];   // W*LSCALE
            ulonglong2 C0=p[4], C1=p[5], C2=p[6], C3=p[7];   // codebook
            float c = csm[v];
            #pragma unroll
            for (int j = 0; j < TPT; j++) {
                u64 q0, q1;
                MUL2(q0, xr[j][0], P0.x);      MUL2(q1, xr[j][1], P0.y);
                FMA2(q0, xr[j][2], P1.x, q0);  FMA2(q1, xr[j][3], P1.y, q1);
                FMA2(q0, xr[j][4], P2.x, q0);  FMA2(q1, xr[j][5], P2.y, q1);
                FMA2(q0, xr[j][6], P3.x, q0);  FMA2(q1, xr[j][7], P3.y, q1);
                ADD2(q0, q0, q1);
                float lo, hi; UNPK2(lo, hi, q0);
                float pw = ex2f((lo + hi) + c);
                s[j] += pw;
                u64 p2; PCK2(p2, pw, pw);
                FMA2(mur[j][0], p2, C0.x, mur[j][0]); FMA2(mur[j][1], p2, C0.y, mur[j][1]);
                FMA2(mur[j][2], p2, C1.x, mur[j][2]); FMA2(mur[j][3], p2, C1.y, mur[j][3]);
                FMA2(mur[j][4], p2, C2.x, mur[j][4]); FMA2(mur[j][5], p2, C2.y, mur[j][5]);
                FMA2(mur[j][6], p2, C3.x, mur[j][6]); FMA2(mur[j][7], p2, C3.y, mur[j][7]);
            }
        }
    }

    // In-CTA slice reduction; write 17-float partial per token to global slot
    #pragma unroll
    for (int j = 0; j < TPT; j++) {
        __syncthreads();
        {
            float* r = smem + tid*17;
            r[0] = s[j];
            #pragma unroll
            for (int i = 0; i < 8; i++) {
                float lo, hi; UNPK2(lo, hi, mur[j][i]);
                r[1+2*i] = lo; r[2+2*i] = hi;
            }
        }
        __syncthreads();
        if (slice == 0) {
            int tok = tok0 + 32*j;
            float S = 0.f, acc[DD];
            #pragma unroll
            for (int d = 0; d < DD; d++) acc[d] = 0.f;
            #pragma unroll
            for (int q = 0; q < SLICE; q++) {
                const float* r = smem + (q*32 + lane)*17;
                S += r[0];
                #pragma unroll
                for (int d = 0; d < DD; d++) acc[d] += r[1+d];
            }
            g_part[(slot*17 + 0)*NTOK + tok] = S;
            #pragma unroll
            for (int d = 0; d < DD; d++)
                g_part[(slot*17 + 1 + d)*NTOK + tok] = acc[d];
        }
    }

    // Cross-CTA combine: last arriving CTA for this tokblock finalizes
    __threadfence();
    __syncthreads();
    if (tid == 0) flag = (atomicAdd(&g_ticket[tb], 1) == VSPLIT - 1);
    __syncthreads();
    if (flag) {
        __threadfence();
        if (tid < TPC) {
            int tok = tb*TPC + tid;
            float S = 0.f, acc[DD];
            #pragma unroll
            for (int d = 0; d < DD; d++) acc[d] = 0.f;
            #pragma unroll
            for (int q = 0; q < VSPLIT; q++) {       // fixed order -> deterministic
                S += __ldcg(&g_part[(q*17 + 0)*NTOK + tok]);
                #pragma unroll
                for (int d = 0; d < DD; d++)
                    acc[d] += __ldcg(&g_part[(q*17 + 1 + d)*NTOK + tok]);
            }
            float invS   = 1.f / S;
            float invden = 1.f / (1.f - t + 1e-10f);
            const float4* xi4 = (const float4*)(x_in + tok*DD);
            const float4* xb4 = (const float4*)(g_x  + tok*DD);
            float4 o[4]; float* of = (float*)o;
            #pragma unroll
            for (int i = 0; i < 4; i++) {
                float4 xi = xi4[i], xbs = xb4[i];
                float xiv[4] = {xi.x, xi.y, xi.z, xi.w};
                float xbv[4] = {xbs.x, xbs.y, xbs.z, xbs.w};
                #pragma unroll
                for (int jj = 0; jj < 4; jj++) {
                    int d = 4*i + jj;
                    of[d] = fmaf(coef, (acc[d]*invS - xiv[jj]) * invden, xbv[jj]);
                }
            }
            float4* xo4 = (float4*)(x_out + tok*DD);
            #pragma unroll
            for (int i = 0; i < 4; i++) xo4[i] = o[i];
        }
        if (tid == 0) g_ticket[tb] = 0;   // clean for next launch / replay
    }
}

// VQ argmin_v ||c_v||^2 - 2 x.c_v
__global__ __launch_bounds__(256)
void quantize_kernel(const float* __restrict__ CB,
                     float* __restrict__ out_x,
                     float* __restrict__ out_idx)
{
    __shared__ __align__(16) float smem[VC*DD + VC];
    float* CBsm = smem;
    float* cn2  = smem + VC*DD;

    int tid   = threadIdx.x;
    int tokl  = tid & 63;
    int slice = tid >> 6;
    int tok   = blockIdx.x * 64 + tokl;

    float x[DD];
    {
        const float4* xi4 = (const float4*)(g_x + tok*DD);
        #pragma unroll
        for (int i = 0; i < 4; i++) {
            float4 v4 = xi4[i];
            x[4*i+0]=v4.x; x[4*i+1]=v4.y; x[4*i+2]=v4.z; x[4*i+3]=v4.w;
        }
    }

    float best = 3.4e38f;
    int   bidx = 0;

    for (int c0 = 0; c0 < VV; c0 += VC) {
        __syncthreads();
        {
            const float4* src = (const float4*)(CB + (size_t)c0*DD);
            float4* dst = (float4*)CBsm;
            for (int j = tid; j < VC*DD/4; j += 256) dst[j] = src[j];
        }
        if (tid < VC) {
            const float* row = CB + (size_t)(c0 + tid)*DD;
            float acc = 0.f;
            #pragma unroll
            for (int d = 0; d < DD; d++) acc = fmaf(row[d], row[d], acc);
            cn2[tid] = acc;
        }
        __syncthreads();

        int vbeg = slice * (VC/4);
        for (int vi = 0; vi < VC/4; vi++) {
            int v = vbeg + vi;
            const float4* cb4 = (const float4*)(CBsm + v*DD);
            float4 cA=cb4[0], cB4=cb4[1], cC=cb4[2], cD4=cb4[3];
            float a0 = x[0]*cA.x  + x[1]*cA.y  + x[2]*cA.z  + x[3]*cA.w;
            float a1 = x[4]*cB4.x + x[5]*cB4.y + x[6]*cB4.z + x[7]*cB4.w;
            float a2 = x[8]*cC.x  + x[9]*cC.y  + x[10]*cC.z + x[11]*cC.w;
            float a3 = x[12]*cD4.x+ x[13]*cD4.y+ x[14]*cD4.z+ x[15]*cD4.w;
            float dist = cn2[v] - 2.f*((a0+a1) + (a2+a3));
            if (dist < best) { best = dist; bidx = c0 + v; }
        }
    }

    __syncthreads();
    float* redf = smem;
    redf[tid*2] = best;
    ((int*)redf)[tid*2 + 1] = bidx;
    __syncthreads();

    if (slice == 0) {
        float bb = best; int bi = bidx;
        #pragma unroll
        for (int q = 1; q < 4; q++) {
            float dq = redf[(tokl + 64*q)*2];
            int   iq = ((int*)redf)[(tokl + 64*q)*2 + 1];
            if (dq < bb || (dq == bb && iq < bi)) { bb = dq; bi = iq; }
        }
        if (out_idx) out_idx[tok] = (float)bi;
        if (out_x) {
            const float4* xi4 = (const float4*)(g_x + tok*DD);
            float4* o4 = (float4*)(out_x + tok*DD);
            #pragma unroll
            for (int i = 0; i < 4; i++) o4[i] = xi4[i];
        }
    }
}

extern "C" void kernel_launch(void* const* d_in, const int* in_sizes, int n_in,
                              void* d_out, int out_size) {
    const float* x0 = (const float*)d_in[0];
    const float* CB = (const float*)d_in[1];
    const float* W  = (const float*)d_in[2];
    const float* b  = (const float*)d_in[3];
    const float* tp = (const float*)d_in[4];

    copy_kernel<<<(NTOK*DD + 255)/256, 256>>>(x0, NTOK*DD);
    prep_kernel<<<VV/256, 256>>>(W, CB);

    const float dt = 1.0f / 7.0f;
    for (int k = 0; k < 7; k++) {
        float t = (float)k / 7.0f;
        velocity_kernel<<<NBLOCKS, NTHREADS>>>(b, tp, t,           0.5f*dt, 0);
        velocity_kernel<<<NBLOCKS, NTHREADS>>>(b, tp, t + 0.5f*dt, dt,      1);
    }

    float* out = (float*)d_out;
    if (out_size >= NTOK*DD + NTOK) {
        quantize_kernel<<<NTOK/64, 256>>>(CB, out, out + NTOK*DD);
    } else if (out_size == NTOK*DD) {
        quantize_kernel<<<NTOK/64, 256>>>(CB, out, nullptr);
    } else {
        quantize_kernel<<<NTOK/64, 256>>>(CB, nullptr, out);
    }
}

// round 6
// speedup vs baseline: 1.1570x; 1.1570x over previous
#include <cuda_runtime.h>

// Fixed shapes: B=32,S=256 -> NTOK=8192; D=16; V=8192; n_steps=8
#define NTOK 8192
#define DD   16
#define VV   8192
#define VC   128            // V-chunk staged in SMEM (double-buffered)
#define TPT  4              // tokens per thread
#define LANES 32
#define SLICE 8             // warps per CTA
#define NTHREADS 256
#define TPC (LANES*TPT)     // 128 tokens per CTA
#define NTB (NTOK/TPC)      // 64 token blocks
#define VSPLIT 4
#define VPER (VV/VSPLIT)    // 2048
#define NCHUNK (VPER/VC)    // 16
#define NBLOCKS (NTB*VSPLIT)// 256 CTAs

#define INVT  1.25f
#define LOG2E 1.4426950408889634f
#define LSCALE (INVT*LOG2E)

typedef unsigned long long u64;
typedef unsigned int u32;

// Scratch (allocation-free rule)
__device__ float g_x   [NTOK*DD];
__device__ float g_xm  [NTOK*DD];
__device__ float g_pack[VV*32];          // [v][0..15]=LSCALE*W[:,v], [v][16..31]=CB[v,:]
__device__ float g_part[VSPLIT*17*NTOK]; // per-slot partials
__device__ int   g_ticket[NTB];          // zero-init; reset by finalizer each launch

__device__ __forceinline__ float ex2f(float x) {
    float r; asm("ex2.approx.ftz.f32 %0, %1;" : "=f"(r) : "f"(x)); return r;
}
#define FMA2(d,a,b,c) asm("fma.rn.f32x2 %0, %1, %2, %3;" : "=l"(d) : "l"(a), "l"(b), "l"(c))
#define MUL2(d,a,b)   asm("mul.rn.f32x2 %0, %1, %2;"     : "=l"(d) : "l"(a), "l"(b))
#define ADD2(d,a,b)   asm("add.rn.f32x2 %0, %1, %2;"     : "=l"(d) : "l"(a), "l"(b))
#define UNPK2(lo,hi,v) asm("mov.b64 {%0,%1}, %2;" : "=f"(lo), "=f"(hi) : "l"(v))
#define PCK2(v,lo,hi)  asm("mov.b64 %0, {%1,%2};" : "=l"(v) : "f"(lo), "f"(hi))

#define CPA16(dst,src)  asm volatile("cp.async.cg.shared.global [%0],[%1],16;" :: "r"(dst), "l"(src))
#define CPA_COMMIT()    asm volatile("cp.async.commit_group;" ::: "memory")
#define CPA_WAIT0()     asm volatile("cp.async.wait_group 0;" ::: "memory")

__global__ void copy_kernel(const float* __restrict__ src, int n) {
    int i = blockIdx.x * blockDim.x + threadIdx.x;
    if (i < n) g_x[i] = src[i];
}

__global__ void prep_kernel(const float* __restrict__ W,   // [DD][VV]
                            const float* __restrict__ CB)  // [VV][DD]
{
    int v = blockIdx.x * blockDim.x + threadIdx.x;
    if (v >= VV) return;
    float wcol[DD];
    #pragma unroll
    for (int d = 0; d < DD; d++) wcol[d] = W[d*VV + v] * LSCALE;
    float4* dst = (float4*)(g_pack + v*32);
    const float4* cb = (const float4*)(CB + v*DD);
    #pragma unroll
    for (int i = 0; i < 4; i++) {
        float4 w4; w4.x=wcol[4*i]; w4.y=wcol[4*i+1]; w4.z=wcol[4*i+2]; w4.w=wcol[4*i+3];
        dst[i]   = w4;
        dst[4+i] = cb[i];
    }
}

// velocity = (softmax((x@W + b + t*tp)/T) @ CB - x)/(1-t+eps); x_out = g_x + coef*v
// No max-subtraction (|log2 logits| <~ 40, fp32-safe).
__global__ __launch_bounds__(NTHREADS)
void velocity_kernel(const float* __restrict__ b,
                     const float* __restrict__ tp,
                     float t, float coef, int mode)
{
    __shared__ __align__(16) float buf[2][VC*32];   // 2 x 16KB double buffer
    __shared__ float csm[2][VC];
    __shared__ int flag;

    const float* x_in  = mode ? g_xm : g_x;
    float*       x_out = mode ? g_x  : g_xm;

    int tid   = threadIdx.x;
    int lane  = tid & 31;
    int slice = tid >> 5;                 // warp 0..7
    int tb    = blockIdx.x >> 2;          // token block 0..63
    int slot  = blockIdx.x & 3;           // V slot 0..3
    int tok0  = tb*TPC + lane;

    // 4 tokens' x as packed f32x2 pairs
    u64 xr[TPT][8], mur[TPT][8];
    u64 zero2; PCK2(zero2, 0.f, 0.f);
    float s[TPT];
    #pragma unroll
    for (int j = 0; j < TPT; j++) {
        const ulonglong2* A = (const ulonglong2*)(x_in + (tok0 + 32*j)*DD);
        #pragma unroll
        for (int i = 0; i < 4; i++) {
            ulonglong2 v2 = A[i];
            xr[j][2*i] = v2.x; xr[j][2*i+1] = v2.y;
        }
        #pragma unroll
        for (int i = 0; i < 8; i++) mur[j][i] = zero2;
        s[j] = 0.f;
    }

    int cbeg = slot * VPER;

    // Prologue: prefetch chunk 0 data + bias
    {
        u32 d0 = (u32)__cvta_generic_to_shared(&buf[0][0]) + tid*16;
        const char* s0 = (const char*)(g_pack + (size_t)cbeg*32) + tid*16;
        #pragma unroll
        for (int k = 0; k < 4; k++) CPA16(d0 + k*NTHREADS*16, s0 + k*NTHREADS*16);
        CPA_COMMIT();
    }
    float rb = 0.f, rtp = 0.f;
    if (tid < VC) { rb = b[cbeg+tid]; rtp = tp[cbeg+tid]; }

    for (int ci = 0; ci < NCHUNK; ci++) {
        int cur = ci & 1;
        CPA_WAIT0();                               // chunk ci landed in buf[cur]
        if (tid < VC) csm[cur][tid] = (rb + t*rtp) * LSCALE;
        __syncthreads();                           // csm visible; buf[cur^1] free

        if (ci + 1 < NCHUNK) {                     // prefetch chunk ci+1
            int c1 = cbeg + (ci+1)*VC;
            u32 d1 = (u32)__cvta_generic_to_shared(&buf[cur^1][0]) + tid*16;
            const char* s1 = (const char*)(g_pack + (size_t)c1*32) + tid*16;
            #pragma unroll
            for (int k = 0; k < 4; k++) CPA16(d1 + k*NTHREADS*16, s1 + k*NTHREADS*16);
            CPA_COMMIT();
            if (tid < VC) { rb = b[c1+tid]; rtp = tp[c1+tid]; }
        }

        const float* bufc = buf[cur];
        const float* csmc = csm[cur];
        int vbeg = slice * (VC/SLICE);             // 16 v per warp per chunk
        #pragma unroll 4
        for (int vi = 0; vi < VC/SLICE; vi++) {
            int v = vbeg + vi;
            const ulonglong2* p = (const ulonglong2*)(bufc + v*32); // warp-broadcast
            ulonglong2 P0=p[0], P1=p[1], P2=p[2], P3=p[3];
            float c = csmc[v];
            u64 cpair; PCK2(cpair, c, 0.f);
            float pw[TPT];
            // phase 1: 4 parallel dot chains
            #pragma unroll
            for (int j = 0; j < TPT; j++) {
                u64 q0 = cpair, q1;
                FMA2(q0, xr[j][0], P0.x, q0);  MUL2(q1, xr[j][1], P0.y);
                FMA2(q0, xr[j][2], P1.x, q0);  FMA2(q1, xr[j][3], P1.y, q1);
                FMA2(q0, xr[j][4], P2.x, q0);  FMA2(q1, xr[j][5], P2.y, q1);
                FMA2(q0, xr[j][6], P3.x, q0);  FMA2(q1, xr[j][7], P3.y, q1);
                ADD2(q0, q0, q1);
                float lo, hi; UNPK2(lo, hi, q0);
                pw[j] = lo + hi;
            }
            ulonglong2 C0=p[4], C1=p[5], C2=p[6], C3=p[7];
            // phase 2: 4 parallel ex2
            #pragma unroll
            for (int j = 0; j < TPT; j++) { pw[j] = ex2f(pw[j]); s[j] += pw[j]; }
            // phase 3: accumulate
            #pragma unroll
            for (int j = 0; j < TPT; j++) {
                u64 p2; PCK2(p2, pw[j], pw[j]);
                FMA2(mur[j][0], p2, C0.x, mur[j][0]); FMA2(mur[j][1], p2, C0.y, mur[j][1]);
                FMA2(mur[j][2], p2, C1.x, mur[j][2]); FMA2(mur[j][3], p2, C1.y, mur[j][3]);
                FMA2(mur[j][4], p2, C2.x, mur[j][4]); FMA2(mur[j][5], p2, C2.y, mur[j][5]);
                FMA2(mur[j][6], p2, C3.x, mur[j][6]); FMA2(mur[j][7], p2, C3.y, mur[j][7]);
            }
        }
        __syncthreads();                           // done with buf[cur] before it refills
    }

    // In-CTA slice reduction; write 17-float partial per token to global slot
    float* red = &buf[0][0];                       // 256*17 = 4352 floats, fits
    #pragma unroll
    for (int j = 0; j < TPT; j++) {
        __syncthreads();
        {
            float* r = red + tid*17;
            r[0] = s[j];
            #pragma unroll
            for (int i = 0; i < 8; i++) {
                float lo, hi; UNPK2(lo, hi, mur[j][i]);
                r[1+2*i] = lo; r[2+2*i] = hi;
            }
        }
        __syncthreads();
        if (slice == 0) {
            int tok = tok0 + 32*j;
            float S = 0.f, acc[DD];
            #pragma unroll
            for (int d = 0; d < DD; d++) acc[d] = 0.f;
            #pragma unroll
            for (int q = 0; q < SLICE; q++) {
                const float* r = red + (q*32 + lane)*17;
                S += r[0];
                #pragma unroll
                for (int d = 0; d < DD; d++) acc[d] += r[1+d];
            }
            g_part[(slot*17 + 0)*NTOK + tok] = S;
            #pragma unroll
            for (int d = 0; d < DD; d++)
                g_part[(slot*17 + 1 + d)*NTOK + tok] = acc[d];
        }
    }

    // Cross-CTA combine: last arriving CTA for this tokblock finalizes
    __threadfence();
    __syncthreads();
    if (tid == 0) flag = (atomicAdd(&g_ticket[tb], 1) == VSPLIT - 1);
    __syncthreads();
    if (flag) {
        __threadfence();
        if (tid < TPC) {
            int tok = tb*TPC + tid;
            float S = 0.f, acc[DD];
            #pragma unroll
            for (int d = 0; d < DD; d++) acc[d] = 0.f;
            #pragma unroll
            for (int q = 0; q < VSPLIT; q++) {       // fixed order -> deterministic
                S += __ldcg(&g_part[(q*17 + 0)*NTOK + tok]);
                #pragma unroll
                for (int d = 0; d < DD; d++)
                    acc[d] += __ldcg(&g_part[(q*17 + 1 + d)*NTOK + tok]);
            }
            float invS   = 1.f / S;
            float invden = 1.f / (1.f - t + 1e-10f);
            const float4* xi4 = (const float4*)(x_in + tok*DD);
            const float4* xb4 = (const float4*)(g_x  + tok*DD);
            float4 o[4]; float* of = (float*)o;
            #pragma unroll
            for (int i = 0; i < 4; i++) {
                float4 xi = xi4[i], xbs = xb4[i];
                float xiv[4] = {xi.x, xi.y, xi.z, xi.w};
                float xbv[4] = {xbs.x, xbs.y, xbs.z, xbs.w};
                #pragma unroll
                for (int jj = 0; jj < 4; jj++) {
                    int d = 4*i + jj;
                    of[d] = fmaf(coef, (acc[d]*invS - xiv[jj]) * invden, xbv[jj]);
                }
            }
            float4* xo4 = (float4*)(x_out + tok*DD);
            #pragma unroll
            for (int i = 0; i < 4; i++) xo4[i] = o[i];
        }
        if (tid == 0) g_ticket[tb] = 0;   // clean for next launch / replay
    }
}

// VQ argmin_v ||c_v||^2 - 2 x.c_v
__global__ __launch_bounds__(256)
void quantize_kernel(const float* __restrict__ CB,
                     float* __restrict__ out_x,
                     float* __restrict__ out_idx)
{
    __shared__ __align__(16) float smem[256*DD + 256];
    float* CBsm = smem;
    float* cn2  = smem + 256*DD;

    int tid   = threadIdx.x;
    int tokl  = tid & 63;
    int slice = tid >> 6;
    int tok   = blockIdx.x * 64 + tokl;

    float x[DD];
    {
        const float4* xi4 = (const float4*)(g_x + tok*DD);
        #pragma unroll
        for (int i = 0; i < 4; i++) {
            float4 v4 = xi4[i];
            x[4*i+0]=v4.x; x[4*i+1]=v4.y; x[4*i+2]=v4.z; x[4*i+3]=v4.w;
        }
    }

    float best = 3.4e38f;
    int   bidx = 0;

    for (int c0 = 0; c0 < VV; c0 += 256) {
        __syncthreads();
        {
            const float4* src = (const float4*)(CB + (size_t)c0*DD);
            float4* dst = (float4*)CBsm;
            for (int j = tid; j < 256*DD/4; j += 256) dst[j] = src[j];
        }
        {
            const float* row = CB + (size_t)(c0 + tid)*DD;
            float acc = 0.f;
            #pragma unroll
            for (int d = 0; d < DD; d++) acc = fmaf(row[d], row[d], acc);
            cn2[tid] = acc;
        }
        __syncthreads();

        int vbeg = slice * 64;
        for (int vi = 0; vi < 64; vi++) {
            int v = vbeg + vi;
            const float4* cb4 = (const float4*)(CBsm + v*DD);
            float4 cA=cb4[0], cB4=cb4[1], cC=cb4[2], cD4=cb4[3];
            float a0 = x[0]*cA.x  + x[1]*cA.y  + x[2]*cA.z  + x[3]*cA.w;
            float a1 = x[4]*cB4.x + x[5]*cB4.y + x[6]*cB4.z + x[7]*cB4.w;
            float a2 = x[8]*cC.x  + x[9]*cC.y  + x[10]*cC.z + x[11]*cC.w;
            float a3 = x[12]*cD4.x+ x[13]*cD4.y+ x[14]*cD4.z+ x[15]*cD4.w;
            float dist = cn2[v] - 2.f*((a0+a1) + (a2+a3));
            if (dist < best) { best = dist; bidx = c0 + v; }
        }
    }

    __syncthreads();
    float* redf = smem;
    redf[tid*2] = best;
    ((int*)redf)[tid*2 + 1] = bidx;
    __syncthreads();

    if (slice == 0) {
        float bb = best; int bi = bidx;
        #pragma unroll
        for (int q = 1; q < 4; q++) {
            float dq = redf[(tokl + 64*q)*2];
            int   iq = ((int*)redf)[(tokl + 64*q)*2 + 1];
            if (dq < bb || (dq == bb && iq < bi)) { bb = dq; bi = iq; }
        }
        if (out_idx) out_idx[tok] = (float)bi;
        if (out_x) {
            const float4* xi4 = (const float4*)(g_x + tok*DD);
            float4* o4 = (float4*)(out_x + tok*DD);
            #pragma unroll
            for (int i = 0; i < 4; i++) o4[i] = xi4[i];
        }
    }
}

extern "C" void kernel_launch(void* const* d_in, const int* in_sizes, int n_in,
                              void* d_out, int out_size) {
    const float* x0 = (const float*)d_in[0];
    const float* CB = (const float*)d_in[1];
    const float* W  = (const float*)d_in[2];
    const float* b  = (const float*)d_in[3];
    const float* tp = (const float*)d_in[4];

    copy_kernel<<<(NTOK*DD + 255)/256, 256>>>(x0, NTOK*DD);
    prep_kernel<<<VV/256, 256>>>(W, CB);

    const float dt = 1.0f / 7.0f;
    for (int k = 0; k < 7; k++) {
        float t = (float)k / 7.0f;
        velocity_kernel<<<NBLOCKS, NTHREADS>>>(b, tp, t,           0.5f*dt, 0);
        velocity_kernel<<<NBLOCKS, NTHREADS>>>(b, tp, t + 0.5f*dt, dt,      1);
    }

    float* out = (float*)d_out;
    if (out_size >= NTOK*DD + NTOK) {
        quantize_kernel<<<NTOK/64, 256>>>(CB, out, out + NTOK*DD);
    } else if (out_size == NTOK*DD) {
        quantize_kernel<<<NTOK/64, 256>>>(CB, out, nullptr);
    } else {
        quantize_kernel<<<NTOK/64, 256>>>(CB, nullptr, out);
    }
}